// round 10
// baseline (speedup 1.0000x reference)
#include <cuda_runtime.h>
#include <cuda_bf16.h>
#include <cstdint>
#include <cstddef>

// Problem constants
#define BB 2
#define TT 2048
#define DD 1024
#define HH 16
#define HD 64
#define D3 3072

// Scratch (allocation-free rule: __device__ globals)
__device__ __nv_bfloat16 g_qkvh[(size_t)BB * TT * D3];
__device__ __nv_bfloat16 g_qkvl[(size_t)BB * TT * D3];
__device__ __nv_bfloat16 g_xh[(size_t)BB * TT * DD];
__device__ __nv_bfloat16 g_xl[(size_t)BB * TT * DD];
__device__ __nv_bfloat16 g_wqh[(size_t)DD * D3];
__device__ __nv_bfloat16 g_wql[(size_t)DD * D3];
__device__ __nv_bfloat16 g_wph[(size_t)DD * DD];
__device__ __nv_bfloat16 g_wpl[(size_t)DD * DD];
__device__ __nv_bfloat16 g_ath[(size_t)BB * TT * DD];
__device__ __nv_bfloat16 g_atl[(size_t)BB * TT * DD];

// ---------------------------------------------------------------------------
// helpers
// ---------------------------------------------------------------------------
__device__ __forceinline__ uint32_t smem_u32(const void* p) {
    uint32_t a;
    asm("{ .reg .u64 t; cvta.to.shared.u64 t, %1; cvt.u32.u64 %0, t; }"
        : "=r"(a) : "l"(p));
    return a;
}
__device__ __forceinline__ void ldsm_x4(uint32_t* r, uint32_t addr) {
    asm volatile("ldmatrix.sync.aligned.m8n8.x4.shared.b16 {%0,%1,%2,%3}, [%4];"
                 : "=r"(r[0]), "=r"(r[1]), "=r"(r[2]), "=r"(r[3]) : "r"(addr));
}
__device__ __forceinline__ void ldsm_x4_t(uint32_t* r, uint32_t addr) {
    asm volatile("ldmatrix.sync.aligned.m8n8.x4.trans.shared.b16 {%0,%1,%2,%3}, [%4];"
                 : "=r"(r[0]), "=r"(r[1]), "=r"(r[2]), "=r"(r[3]) : "r"(addr));
}
__device__ __forceinline__ void mma_bf16(float* d, const uint32_t* a, const uint32_t* b) {
    asm volatile("mma.sync.aligned.m16n8k16.row.col.f32.bf16.bf16.f32 "
                 "{%0,%1,%2,%3}, {%4,%5,%6,%7}, {%8,%9}, {%0,%1,%2,%3};"
                 : "+f"(d[0]), "+f"(d[1]), "+f"(d[2]), "+f"(d[3])
                 : "r"(a[0]), "r"(a[1]), "r"(a[2]), "r"(a[3]),
                   "r"(b[0]), "r"(b[1]));
}
__device__ __forceinline__ void cp16(uint32_t smem_dst, const void* gsrc) {
    asm volatile("cp.async.cg.shared.global [%0], [%1], 16;"
                 :: "r"(smem_dst), "l"(gsrc));
}
__device__ __forceinline__ void cp16z(uint32_t smem_dst, const void* gsrc, bool valid) {
    const int sz = valid ? 16 : 0;
    asm volatile("cp.async.cg.shared.global [%0], [%1], 16, %2;"
                 :: "r"(smem_dst), "l"(gsrc), "r"(sz));
}
__device__ __forceinline__ void cp_commit() {
    asm volatile("cp.async.commit_group;" ::: "memory");
}
template <int N>
__device__ __forceinline__ void cp_wait() {
    asm volatile("cp.async.wait_group %0;" :: "n"(N) : "memory");
}
__device__ __forceinline__ void cvt8(const float4 v, uint2& hi, uint2& lo) {
    __nv_bfloat162 h0 = __floats2bfloat162_rn(v.x, v.y);
    __nv_bfloat162 h1 = __floats2bfloat162_rn(v.z, v.w);
    __nv_bfloat162 l0 = __floats2bfloat162_rn(v.x - __bfloat162float(h0.x),
                                              v.y - __bfloat162float(h0.y));
    __nv_bfloat162 l1 = __floats2bfloat162_rn(v.z - __bfloat162float(h1.x),
                                              v.w - __bfloat162float(h1.y));
    hi.x = *(uint32_t*)&h0; hi.y = *(uint32_t*)&h1;
    lo.x = *(uint32_t*)&l0; lo.y = *(uint32_t*)&l1;
}
__device__ __forceinline__ uint32_t pack_hi2(float a, float b) {
    __nv_bfloat162 t = __floats2bfloat162_rn(a, b);
    return *(uint32_t*)&t;
}
__device__ __forceinline__ uint32_t pack_lo2(float a, float b, uint32_t hi) {
    __nv_bfloat162 h = *(__nv_bfloat162*)&hi;
    __nv_bfloat162 t = __floats2bfloat162_rn(a - __bfloat162float(h.x),
                                             b - __bfloat162float(h.y));
    return *(uint32_t*)&t;
}

// ---------------------------------------------------------------------------
// fused fp32 -> (bf16 hi, bf16 lo) for all three inputs in ONE launch
// ---------------------------------------------------------------------------
#define N4_X  ((BB * TT * DD) / 4)
#define N4_WQ ((DD * D3) / 4)
#define N4_WP ((DD * DD) / 4)

__global__ __launch_bounds__(256)
void cvt3(const float* __restrict__ x, const float* __restrict__ wq,
          const float* __restrict__ wp,
          __nv_bfloat16* __restrict__ xh, __nv_bfloat16* __restrict__ xl,
          __nv_bfloat16* __restrict__ wqh, __nv_bfloat16* __restrict__ wql,
          __nv_bfloat16* __restrict__ wph, __nv_bfloat16* __restrict__ wpl)
{
    const int stride = gridDim.x * blockDim.x;
    const int t0 = blockIdx.x * blockDim.x + threadIdx.x;
    for (int i = t0; i < N4_X; i += stride) {
        uint2 h, l; cvt8(((const float4*)x)[i], h, l);
        ((uint2*)xh)[i] = h; ((uint2*)xl)[i] = l;
    }
    for (int i = t0; i < N4_WQ; i += stride) {
        uint2 h, l; cvt8(((const float4*)wq)[i], h, l);
        ((uint2*)wqh)[i] = h; ((uint2*)wql)[i] = l;
    }
    for (int i = t0; i < N4_WP; i += stride) {
        uint2 h, l; cvt8(((const float4*)wp)[i], h, l);
        ((uint2*)wph)[i] = h; ((uint2*)wpl)[i] = l;
    }
}

// ---------------------------------------------------------------------------
// bf16-split GEMM v4: 128x128 CTA tile, 8 warps (2x4) of 64x32, K-chunk 32,
// 3-stage cp.async ring, 2 CTAs/SM (regs capped at 128).
// ---------------------------------------------------------------------------
#define A_STRIDE 40
#define B_STRIDE 136
#define A_BYTES  (128 * A_STRIDE * 2)              // 10240
#define B_BYTES  (32 * B_STRIDE * 2)               // 8704
#define OFF_AL   A_BYTES
#define OFF_BH   (2 * A_BYTES)
#define OFF_BL   (2 * A_BYTES + B_BYTES)
#define STAGE_BYTES (2 * A_BYTES + 2 * B_BYTES)    // 37888
#define NSTAGE 3
#define GEMM_SMEM (NSTAGE * STAGE_BYTES)           // 113664

__global__ __launch_bounds__(256, 2)
void gemm_bf16x3(const __nv_bfloat16* __restrict__ Ah, const __nv_bfloat16* __restrict__ Al,
                 const __nv_bfloat16* __restrict__ Bh, const __nv_bfloat16* __restrict__ Bl,
                 float* __restrict__ C,
                 __nv_bfloat16* __restrict__ Ch, __nv_bfloat16* __restrict__ Cl,
                 int M, int N, int K,
                 const float* __restrict__ bias)
{
    extern __shared__ char sm[];
    const uint32_t sb = smem_u32(sm);
    const int tid = threadIdx.x;
    const int lane = tid & 31, wid = tid >> 5;
    const int wm = wid & 1, wn = wid >> 1;          // 2 (m) x 4 (n)
    const int m0 = blockIdx.y * 128, n0 = blockIdx.x * 128;
    const int NC = K >> 5;

    // cp.async roles
    const int arow = tid >> 2, aseg = tid & 3;       // A: rows arow, arow+64
    const int brow = tid >> 4, bseg = tid & 15;      // B: rows brow, brow+16

    const __nv_bfloat16* gAh = Ah + (size_t)(m0 + arow) * K + aseg * 8;
    const __nv_bfloat16* gAl = Al + (size_t)(m0 + arow) * K + aseg * 8;
    const __nv_bfloat16* gBh = Bh + (size_t)brow * N + n0 + bseg * 8;
    const __nv_bfloat16* gBl = Bl + (size_t)brow * N + n0 + bseg * 8;
    const uint32_t dA = arow * (A_STRIDE * 2) + aseg * 16;
    const uint32_t dB = brow * (B_STRIDE * 2) + bseg * 16;

    float acc[4][4][4];
    #pragma unroll
    for (int mt = 0; mt < 4; ++mt)
        #pragma unroll
        for (int nt = 0; nt < 4; ++nt)
            #pragma unroll
            for (int q = 0; q < 4; ++q) acc[mt][nt][q] = 0.f;

    auto issue = [&](int cc, int st) {
        const uint32_t stb = sb + (uint32_t)st * STAGE_BYTES;
        const size_t ka = (size_t)cc * 32;
        #pragma unroll
        for (int i = 0; i < 2; ++i) {
            cp16(stb + dA + i * 64 * (A_STRIDE * 2),          gAh + ka + (size_t)i * 64 * K);
            cp16(stb + OFF_AL + dA + i * 64 * (A_STRIDE * 2), gAl + ka + (size_t)i * 64 * K);
        }
        const size_t kb = (size_t)cc * 32 * N;
        #pragma unroll
        for (int i = 0; i < 2; ++i) {
            cp16(stb + OFF_BH + dB + i * 16 * (B_STRIDE * 2), gBh + kb + (size_t)i * 16 * N);
            cp16(stb + OFF_BL + dB + i * 16 * (B_STRIDE * 2), gBl + kb + (size_t)i * 16 * N);
        }
        cp_commit();
    };

    issue(0, 0);
    if (NC > 1) issue(1, 1);

    const uint32_t aRow = ((wm * 64 + (lane & 15)) * A_STRIDE + (lane >> 4) * 8) * 2;
    const int km = (lane & 7) + ((lane >> 3) & 1) * 8;
    const uint32_t bCol = OFF_BH + (km * B_STRIDE + wn * 32 + (lane >> 4) * 8) * 2;

    for (int c = 0; c < NC; ++c) {
        if (c + 1 < NC) cp_wait<1>();
        else cp_wait<0>();
        __syncthreads();
        // stage (c+2)%3 == (c-1)%3: its readers all passed the sync above
        if (c + 2 < NC) issue(c + 2, (c + 2) % 3);

        const uint32_t stb = sb + (uint32_t)(c % 3) * STAGE_BYTES;
        #pragma unroll
        for (int ks = 0; ks < 2; ++ks) {
            const int k0 = ks * 16;
            uint32_t ahr[4][4], alr[4][4];
            #pragma unroll
            for (int mt = 0; mt < 4; ++mt) {
                ldsm_x4(ahr[mt], stb + aRow + (mt * 16 * A_STRIDE + k0) * 2);
                ldsm_x4(alr[mt], stb + OFF_AL + aRow + (mt * 16 * A_STRIDE + k0) * 2);
            }
            uint32_t bh[8], bl[8];
            #pragma unroll
            for (int j = 0; j < 2; ++j) {
                ldsm_x4_t(bh + j * 4, stb + bCol + (k0 * B_STRIDE + j * 16) * 2);
                ldsm_x4_t(bl + j * 4, stb + B_BYTES + bCol + (k0 * B_STRIDE + j * 16) * 2);
            }
            #pragma unroll
            for (int mt = 0; mt < 4; ++mt)
                #pragma unroll
                for (int nt = 0; nt < 4; ++nt) {
                    mma_bf16(acc[mt][nt], ahr[mt], bh + nt * 2);
                    mma_bf16(acc[mt][nt], ahr[mt], bl + nt * 2);
                    mma_bf16(acc[mt][nt], alr[mt], bh + nt * 2);
                }
        }
    }

    const int row = m0 + wm * 64 + (lane >> 2);
    const int colb = n0 + wn * 32 + (lane & 3) * 2;
    #pragma unroll
    for (int nt = 0; nt < 4; ++nt) {
        float2 bv = make_float2(0.f, 0.f);
        if (bias) bv = *(const float2*)(bias + colb + nt * 8);
        #pragma unroll
        for (int mt = 0; mt < 4; ++mt) {
            const float* d = acc[mt][nt];
            const float v00 = d[0] + bv.x, v01 = d[1] + bv.y;
            const float v10 = d[2] + bv.x, v11 = d[3] + bv.y;
            const size_t i0 = (size_t)(row + mt * 16) * N + colb + nt * 8;
            const size_t i1 = (size_t)(row + mt * 16 + 8) * N + colb + nt * 8;
            if (Ch) {
                uint32_t h0 = pack_hi2(v00, v01), l0 = pack_lo2(v00, v01, h0);
                uint32_t h1 = pack_hi2(v10, v11), l1 = pack_lo2(v10, v11, h1);
                *(uint32_t*)&Ch[i0] = h0; *(uint32_t*)&Cl[i0] = l0;
                *(uint32_t*)&Ch[i1] = h1; *(uint32_t*)&Cl[i1] = l1;
            } else {
                *(float2*)&C[i0] = make_float2(v00, v01);
                *(float2*)&C[i1] = make_float2(v10, v11);
            }
        }
    }
}

// ---------------------------------------------------------------------------
// Tensor-core sparse attention (unchanged R9 win).
// ---------------------------------------------------------------------------
#define KSTR 72
#define SQH 0
#define SQL (64 * KSTR * 2)
#define SKH (2 * 64 * KSTR * 2)
#define SKL (SKH + 224 * KSTR * 2)
#define SVH (SKL + 224 * KSTR * 2)
#define SVL (SVH + 224 * KSTR * 2)
#define SRED (SVL + 224 * KSTR * 2)
#define SO  SKH
#define ATTN_SMEM (SRED + 1024)

__global__ __launch_bounds__(256, 1)
void attn_mma(const __nv_bfloat16* __restrict__ qh_, const __nv_bfloat16* __restrict__ ql_,
              __nv_bfloat16* __restrict__ oh, __nv_bfloat16* __restrict__ ol)
{
    const int t0 = blockIdx.x * 64;
    const int h  = blockIdx.y;
    const int b  = blockIdx.z;
    const int tid = threadIdx.x;
    const int lane = tid & 31, wid = tid >> 5;
    const int mtile = wid & 3, half = wid >> 2;

    extern __shared__ char sm[];
    const uint32_t sb = smem_u32(sm);
    const size_t baseBT = (size_t)b * TT;
    const int hoff = h * HD;

    for (int idx = tid; idx < 64 * 8; idx += 256) {
        const int r = idx >> 3, c = (idx & 7) * 8;
        const size_t go = (baseBT + t0 + r) * D3 + hoff + c;
        const uint32_t off = (r * KSTR + c) * 2;
        cp16(sb + SQH + off, qh_ + go);
        cp16(sb + SQL + off, ql_ + go);
    }
    for (int idx = tid; idx < 224 * 8; idx += 256) {
        const int r = idx >> 3, c = (idx & 7) * 8;
        int t = 0; bool valid = false;
        if (r < 128)      { t = r * 16;              valid = true; }
        else if (r < 207) { t = t0 - 15 + (r - 128); valid = (t >= 0); }
        if (t < 0) t = 0;
        const size_t go = (baseBT + t) * D3 + hoff + c;
        const uint32_t off = (r * KSTR + c) * 2;
        cp16z(sb + SKH + off, qh_ + go + 1024, valid);
        cp16z(sb + SKL + off, ql_ + go + 1024, valid);
        cp16z(sb + SVH + off, qh_ + go + 2048, valid);
        cp16z(sb + SVL + off, ql_ + go + 2048, valid);
    }
    cp_commit();
    cp_wait<0>();
    __syncthreads();

    uint32_t qh[4][4], ql[4][4];
    const uint32_t aQ = sb + SQH + ((mtile * 16 + (lane & 15)) * KSTR + (lane >> 4) * 8) * 2;
    #pragma unroll
    for (int kc = 0; kc < 4; ++kc) {
        ldsm_x4(qh[kc], aQ + kc * 32);
        ldsm_x4(ql[kc], aQ + (SQL - SQH) + kc * 32);
    }

    const uint32_t bK = sb + SKH +
        ((half * 112 + (lane & 7) + ((lane >> 4) & 1) * 8) * KSTR + ((lane >> 3) & 1) * 8) * 2;

    float cf[14][4];
    #pragma unroll
    for (int j = 0; j < 14; ++j)
        #pragma unroll
        for (int e = 0; e < 4; ++e) cf[j][e] = 0.f;

    #pragma unroll
    for (int jj = 0; jj < 7; ++jj) {
        #pragma unroll
        for (int kc = 0; kc < 4; ++kc) {
            uint32_t kh4[4], kl4[4];
            const uint32_t ad = bK + (jj * 16 * KSTR + kc * 16) * 2;
            ldsm_x4(kh4, ad);
            ldsm_x4(kl4, ad + (SKL - SKH));
            mma_bf16(cf[2 * jj],     qh[kc], kh4 + 0);
            mma_bf16(cf[2 * jj],     qh[kc], kl4 + 0);
            mma_bf16(cf[2 * jj],     ql[kc], kh4 + 0);
            mma_bf16(cf[2 * jj + 1], qh[kc], kh4 + 2);
            mma_bf16(cf[2 * jj + 1], qh[kc], kl4 + 2);
            mma_bf16(cf[2 * jj + 1], ql[kc], kh4 + 2);
        }
    }
    #pragma unroll
    for (int j = 0; j < 14; ++j)
        #pragma unroll
        for (int e = 0; e < 4; ++e) cf[j][e] *= 0.125f;

    const int r0 = mtile * 16 + (lane >> 2);
    const int r1 = r0 + 8;
    float* sMax = (float*)(sm + SRED);
    float* sSum = (float*)(sm + SRED + 512);
    const int jg = (half == 0) ? 14 : 2;

    float gm0 = -1e30f, gm1 = -1e30f;
    for (int j = 0; j < jg; ++j) {
        gm0 = fmaxf(gm0, fmaxf(cf[j][0], cf[j][1]));
        gm1 = fmaxf(gm1, fmaxf(cf[j][2], cf[j][3]));
    }
    gm0 = fmaxf(gm0, __shfl_xor_sync(0xffffffffu, gm0, 1));
    gm0 = fmaxf(gm0, __shfl_xor_sync(0xffffffffu, gm0, 2));
    gm1 = fmaxf(gm1, __shfl_xor_sync(0xffffffffu, gm1, 1));
    gm1 = fmaxf(gm1, __shfl_xor_sync(0xffffffffu, gm1, 2));
    if ((lane & 3) == 0) { sMax[half * 64 + r0] = gm0; sMax[half * 64 + r1] = gm1; }
    __syncthreads();
    const float M0 = fmaxf(sMax[r0], sMax[64 + r0]);
    const float M1 = fmaxf(sMax[r1], sMax[64 + r1]);

    float gs0 = 0.f, gs1 = 0.f;
    for (int j = 0; j < jg; ++j) {
        cf[j][0] = __expf(cf[j][0] - M0); cf[j][1] = __expf(cf[j][1] - M0);
        cf[j][2] = __expf(cf[j][2] - M1); cf[j][3] = __expf(cf[j][3] - M1);
        gs0 += cf[j][0] + cf[j][1];
        gs1 += cf[j][2] + cf[j][3];
    }
    gs0 += __shfl_xor_sync(0xffffffffu, gs0, 1);
    gs0 += __shfl_xor_sync(0xffffffffu, gs0, 2);
    gs1 += __shfl_xor_sync(0xffffffffu, gs1, 1);
    gs1 += __shfl_xor_sync(0xffffffffu, gs1, 2);
    if ((lane & 3) == 0) { sSum[half * 64 + r0] = gs0; sSum[half * 64 + r1] = gs1; }

    if (half == 1) {
        float lm0 = -1e30f, lm1 = -1e30f;
        #pragma unroll
        for (int j = 2; j < 14; ++j) {
            const int c0 = (14 + j) * 8 + (lane & 3) * 2 - 128;
            const int c1 = c0 + 1;
            if ((unsigned)(c0 - r0) > 15u) cf[j][0] = -1e30f;
            if ((unsigned)(c1 - r0) > 15u) cf[j][1] = -1e30f;
            if ((unsigned)(c0 - r1) > 15u) cf[j][2] = -1e30f;
            if ((unsigned)(c1 - r1) > 15u) cf[j][3] = -1e30f;
            lm0 = fmaxf(lm0, fmaxf(cf[j][0], cf[j][1]));
            lm1 = fmaxf(lm1, fmaxf(cf[j][2], cf[j][3]));
        }
        lm0 = fmaxf(lm0, __shfl_xor_sync(0xffffffffu, lm0, 1));
        lm0 = fmaxf(lm0, __shfl_xor_sync(0xffffffffu, lm0, 2));
        lm1 = fmaxf(lm1, __shfl_xor_sync(0xffffffffu, lm1, 1));
        lm1 = fmaxf(lm1, __shfl_xor_sync(0xffffffffu, lm1, 2));
        float ls0 = 0.f, ls1 = 0.f;
        #pragma unroll
        for (int j = 2; j < 14; ++j) {
            cf[j][0] = __expf(cf[j][0] - lm0); cf[j][1] = __expf(cf[j][1] - lm0);
            cf[j][2] = __expf(cf[j][2] - lm1); cf[j][3] = __expf(cf[j][3] - lm1);
            ls0 += cf[j][0] + cf[j][1];
            ls1 += cf[j][2] + cf[j][3];
        }
        ls0 += __shfl_xor_sync(0xffffffffu, ls0, 1);
        ls0 += __shfl_xor_sync(0xffffffffu, ls0, 2);
        ls1 += __shfl_xor_sync(0xffffffffu, ls1, 1);
        ls1 += __shfl_xor_sync(0xffffffffu, ls1, 2);
        const float il0 = 1.f / ls0, il1 = 1.f / ls1;
        #pragma unroll
        for (int j = 2; j < 14; ++j) {
            cf[j][0] *= il0; cf[j][1] *= il0;
            cf[j][2] *= il1; cf[j][3] *= il1;
        }
    }
    __syncthreads();
    const float iv0 = 1.f / (sSum[r0] + sSum[64 + r0]);
    const float iv1 = 1.f / (sSum[r1] + sSum[64 + r1]);
    for (int j = 0; j < jg; ++j) {
        cf[j][0] *= iv0; cf[j][1] *= iv0;
        cf[j][2] *= iv1; cf[j][3] *= iv1;
    }

    float of[8][4];
    #pragma unroll
    for (int nt = 0; nt < 8; ++nt)
        #pragma unroll
        for (int e = 0; e < 4; ++e) of[nt][e] = 0.f;

    const int km = (lane & 7) + ((lane >> 3) & 1) * 8;
    const uint32_t bV = sb + SVH + ((half * 112 + km) * KSTR + (lane >> 4) * 8) * 2;

    #pragma unroll
    for (int kc2 = 0; kc2 < 7; ++kc2) {
        const int j0 = 2 * kc2, j1 = j0 + 1;
        uint32_t ph[4], pl[4];
        ph[0] = pack_hi2(cf[j0][0], cf[j0][1]); pl[0] = pack_lo2(cf[j0][0], cf[j0][1], ph[0]);
        ph[1] = pack_hi2(cf[j0][2], cf[j0][3]); pl[1] = pack_lo2(cf[j0][2], cf[j0][3], ph[1]);
        ph[2] = pack_hi2(cf[j1][0], cf[j1][1]); pl[2] = pack_lo2(cf[j1][0], cf[j1][1], ph[2]);
        ph[3] = pack_hi2(cf[j1][2], cf[j1][3]); pl[3] = pack_lo2(cf[j1][2], cf[j1][3], ph[3]);
        #pragma unroll
        for (int nd2 = 0; nd2 < 4; ++nd2) {
            uint32_t vh4[4], vl4[4];
            const uint32_t ad = bV + (kc2 * 16 * KSTR + nd2 * 16) * 2;
            ldsm_x4_t(vh4, ad);
            ldsm_x4_t(vl4, ad + (SVL - SVH));
            mma_bf16(of[2 * nd2],     ph, vh4 + 0);
            mma_bf16(of[2 * nd2],     ph, vl4 + 0);
            mma_bf16(of[2 * nd2],     pl, vh4 + 0);
            mma_bf16(of[2 * nd2 + 1], ph, vh4 + 2);
            mma_bf16(of[2 * nd2 + 1], ph, vl4 + 2);
            mma_bf16(of[2 * nd2 + 1], pl, vh4 + 2);
        }
    }

    float* sO = (float*)(sm + SO);
    const int rl = lane >> 2, cb = (lane & 3) * 2;
    const int base0 = ((half * 4 + mtile) * 16 + rl) * 64;
    #pragma unroll
    for (int nt = 0; nt < 8; ++nt) {
        sO[base0 + nt * 8 + cb]     = of[nt][0];
        sO[base0 + nt * 8 + cb + 1] = of[nt][1];
        sO[base0 + 8 * 64 + nt * 8 + cb]     = of[nt][2];
        sO[base0 + 8 * 64 + nt * 8 + cb + 1] = of[nt][3];
    }
    __syncthreads();

    const int qi = tid >> 2, cg = (tid & 3) * 16;
    #pragma unroll
    for (int i = 0; i < 4; ++i) {
        const int c = cg + i * 4;
        const float4 a = *(float4*)&sO[qi * 64 + c];
        const float4 bq = *(float4*)&sO[(64 + qi) * 64 + c];
        float4 o = make_float4(a.x + bq.x, a.y + bq.y, a.z + bq.z, a.w + bq.w);
        uint2 hi, lo; cvt8(o, hi, lo);
        const size_t off = (baseBT + t0 + qi) * DD + hoff + c;
        *(uint2*)&oh[off] = hi;
        *(uint2*)&ol[off] = lo;
    }
}

// ---------------------------------------------------------------------------
extern "C" void kernel_launch(void* const* d_in, const int* in_sizes, int n_in,
                              void* d_out, int out_size)
{
    const float* x      = (const float*)d_in[0];
    const float* w_qkv  = (const float*)d_in[1];
    const float* w_proj = (const float*)d_in[2];
    const float* b_proj = (const float*)d_in[3];
    float* out = (float*)d_out;

    __nv_bfloat16 *qkvh, *qkvl, *xh, *xl, *wqh, *wql, *wph, *wpl, *ath, *atl;
    cudaGetSymbolAddress((void**)&qkvh, g_qkvh);
    cudaGetSymbolAddress((void**)&qkvl, g_qkvl);
    cudaGetSymbolAddress((void**)&xh,  g_xh);
    cudaGetSymbolAddress((void**)&xl,  g_xl);
    cudaGetSymbolAddress((void**)&wqh, g_wqh);
    cudaGetSymbolAddress((void**)&wql, g_wql);
    cudaGetSymbolAddress((void**)&wph, g_wph);
    cudaGetSymbolAddress((void**)&wpl, g_wpl);
    cudaGetSymbolAddress((void**)&ath, g_ath);
    cudaGetSymbolAddress((void**)&atl, g_atl);

    const int M = BB * TT;  // 4096

    cudaFuncSetAttribute(gemm_bf16x3, cudaFuncAttributeMaxDynamicSharedMemorySize, GEMM_SMEM);
    cudaFuncSetAttribute(attn_mma, cudaFuncAttributeMaxDynamicSharedMemorySize, ATTN_SMEM);

    // 0) split all inputs/weights into bf16 hi/lo (one launch)
    cvt3<<<1184, 256>>>(x, w_qkv, w_proj, xh, xl, wqh, wql, wph, wpl);

    // 1) qkv = x @ w_qkv  (bf16 hi/lo out)
    gemm_bf16x3<<<dim3(D3 / 128, M / 128), 256, GEMM_SMEM>>>(
        xh, xl, wqh, wql, nullptr, qkvh, qkvl, M, D3, DD, nullptr);

    // 2) tensor-core sparse attention
    attn_mma<<<dim3(TT / 64, HH, BB), 256, ATTN_SMEM>>>(qkvh, qkvl, ath, atl);

    // 3) out = attn @ w_proj + b_proj (fp32 out)
    gemm_bf16x3<<<dim3(DD / 128, M / 128), 256, GEMM_SMEM>>>(
        ath, atl, wph, wpl, out, nullptr, nullptr, M, DD, DD, b_proj);
}

// round 11
// speedup vs baseline: 1.5018x; 1.5018x over previous
#include <cuda_runtime.h>
#include <cuda_bf16.h>
#include <cstdint>
#include <cstddef>

// Problem constants
#define BB 2
#define TT 2048
#define DD 1024
#define HH 16
#define HD 64
#define D3 3072

// Scratch (allocation-free rule: __device__ globals)
__device__ __nv_bfloat16 g_qkvh[(size_t)BB * TT * D3];
__device__ __nv_bfloat16 g_qkvl[(size_t)BB * TT * D3];
__device__ __nv_bfloat16 g_xh[(size_t)BB * TT * DD];
__device__ __nv_bfloat16 g_xl[(size_t)BB * TT * DD];
__device__ __nv_bfloat16 g_wqh[(size_t)DD * D3];
__device__ __nv_bfloat16 g_wql[(size_t)DD * D3];
__device__ __nv_bfloat16 g_wph[(size_t)DD * DD];
__device__ __nv_bfloat16 g_wpl[(size_t)DD * DD];
__device__ __nv_bfloat16 g_ath[(size_t)BB * TT * DD];
__device__ __nv_bfloat16 g_atl[(size_t)BB * TT * DD];

// ---------------------------------------------------------------------------
// helpers
// ---------------------------------------------------------------------------
__device__ __forceinline__ uint32_t smem_u32(const void* p) {
    uint32_t a;
    asm("{ .reg .u64 t; cvta.to.shared.u64 t, %1; cvt.u32.u64 %0, t; }"
        : "=r"(a) : "l"(p));
    return a;
}
__device__ __forceinline__ void ldsm_x4(uint32_t* r, uint32_t addr) {
    asm volatile("ldmatrix.sync.aligned.m8n8.x4.shared.b16 {%0,%1,%2,%3}, [%4];"
                 : "=r"(r[0]), "=r"(r[1]), "=r"(r[2]), "=r"(r[3]) : "r"(addr));
}
__device__ __forceinline__ void ldsm_x4_t(uint32_t* r, uint32_t addr) {
    asm volatile("ldmatrix.sync.aligned.m8n8.x4.trans.shared.b16 {%0,%1,%2,%3}, [%4];"
                 : "=r"(r[0]), "=r"(r[1]), "=r"(r[2]), "=r"(r[3]) : "r"(addr));
}
__device__ __forceinline__ void mma_bf16(float* d, const uint32_t* a, const uint32_t* b) {
    asm volatile("mma.sync.aligned.m16n8k16.row.col.f32.bf16.bf16.f32 "
                 "{%0,%1,%2,%3}, {%4,%5,%6,%7}, {%8,%9}, {%0,%1,%2,%3};"
                 : "+f"(d[0]), "+f"(d[1]), "+f"(d[2]), "+f"(d[3])
                 : "r"(a[0]), "r"(a[1]), "r"(a[2]), "r"(a[3]),
                   "r"(b[0]), "r"(b[1]));
}
__device__ __forceinline__ void cp16(uint32_t smem_dst, const void* gsrc) {
    asm volatile("cp.async.cg.shared.global [%0], [%1], 16;"
                 :: "r"(smem_dst), "l"(gsrc));
}
__device__ __forceinline__ void cp16z(uint32_t smem_dst, const void* gsrc, bool valid) {
    const int sz = valid ? 16 : 0;
    asm volatile("cp.async.cg.shared.global [%0], [%1], 16, %2;"
                 :: "r"(smem_dst), "l"(gsrc), "r"(sz));
}
__device__ __forceinline__ void cp_commit() {
    asm volatile("cp.async.commit_group;" ::: "memory");
}
template <int N>
__device__ __forceinline__ void cp_wait() {
    asm volatile("cp.async.wait_group %0;" :: "n"(N) : "memory");
}
__device__ __forceinline__ void cvt8(const float4 v, uint2& hi, uint2& lo) {
    __nv_bfloat162 h0 = __floats2bfloat162_rn(v.x, v.y);
    __nv_bfloat162 h1 = __floats2bfloat162_rn(v.z, v.w);
    __nv_bfloat162 l0 = __floats2bfloat162_rn(v.x - __bfloat162float(h0.x),
                                              v.y - __bfloat162float(h0.y));
    __nv_bfloat162 l1 = __floats2bfloat162_rn(v.z - __bfloat162float(h1.x),
                                              v.w - __bfloat162float(h1.y));
    hi.x = *(uint32_t*)&h0; hi.y = *(uint32_t*)&h1;
    lo.x = *(uint32_t*)&l0; lo.y = *(uint32_t*)&l1;
}
__device__ __forceinline__ uint32_t pack_hi2(float a, float b) {
    __nv_bfloat162 t = __floats2bfloat162_rn(a, b);
    return *(uint32_t*)&t;
}
__device__ __forceinline__ uint32_t pack_lo2(float a, float b, uint32_t hi) {
    __nv_bfloat162 h = *(__nv_bfloat162*)&hi;
    __nv_bfloat162 t = __floats2bfloat162_rn(a - __bfloat162float(h.x),
                                             b - __bfloat162float(h.y));
    return *(uint32_t*)&t;
}

// ---------------------------------------------------------------------------
// fused fp32 -> (bf16 hi, bf16 lo) for all three inputs in ONE launch
// ---------------------------------------------------------------------------
#define N4_X  ((BB * TT * DD) / 4)
#define N4_WQ ((DD * D3) / 4)
#define N4_WP ((DD * DD) / 4)

__global__ __launch_bounds__(256)
void cvt3(const float* __restrict__ x, const float* __restrict__ wq,
          const float* __restrict__ wp,
          __nv_bfloat16* __restrict__ xh, __nv_bfloat16* __restrict__ xl,
          __nv_bfloat16* __restrict__ wqh, __nv_bfloat16* __restrict__ wql,
          __nv_bfloat16* __restrict__ wph, __nv_bfloat16* __restrict__ wpl)
{
    const int stride = gridDim.x * blockDim.x;
    const int t0 = blockIdx.x * blockDim.x + threadIdx.x;
    for (int i = t0; i < N4_X; i += stride) {
        uint2 h, l; cvt8(((const float4*)x)[i], h, l);
        ((uint2*)xh)[i] = h; ((uint2*)xl)[i] = l;
    }
    for (int i = t0; i < N4_WQ; i += stride) {
        uint2 h, l; cvt8(((const float4*)wq)[i], h, l);
        ((uint2*)wqh)[i] = h; ((uint2*)wql)[i] = l;
    }
    for (int i = t0; i < N4_WP; i += stride) {
        uint2 h, l; cvt8(((const float4*)wp)[i], h, l);
        ((uint2*)wph)[i] = h; ((uint2*)wpl)[i] = l;
    }
}

// ---------------------------------------------------------------------------
// bf16-split GEMM v5: 128x256 CTA tile, 512 threads, 16 warps (4x4) of 32x64,
// K-chunk 32, 4-stage cp.async ring, one barrier per chunk.
// ---------------------------------------------------------------------------
#define A_STRIDE 40
#define B_STRIDE 264
#define A_BYTES  (128 * A_STRIDE * 2)
#define B_BYTES  (32 * B_STRIDE * 2)
#define OFF_AL   A_BYTES
#define OFF_BH   (2 * A_BYTES)
#define OFF_BL   (2 * A_BYTES + B_BYTES)
#define STAGE_BYTES (2 * A_BYTES + 2 * B_BYTES)   // 54272
#define NSTAGE 4
#define GEMM_SMEM (NSTAGE * STAGE_BYTES)          // 217088

__global__ __launch_bounds__(512, 1)
void gemm_bf16x3(const __nv_bfloat16* __restrict__ Ah, const __nv_bfloat16* __restrict__ Al,
                 const __nv_bfloat16* __restrict__ Bh, const __nv_bfloat16* __restrict__ Bl,
                 float* __restrict__ C,
                 __nv_bfloat16* __restrict__ Ch, __nv_bfloat16* __restrict__ Cl,
                 int M, int N, int K,
                 const float* __restrict__ bias)
{
    extern __shared__ char sm[];
    const uint32_t sb = smem_u32(sm);
    const int tid = threadIdx.x;
    const int lane = tid & 31, wid = tid >> 5;
    const int wm = wid & 3, wn = wid >> 2;          // 4 (m) x 4 (n)
    const int m0 = blockIdx.y * 128, n0 = blockIdx.x * 256;
    const int NC = K >> 5;

    // cp.async roles (512 threads)
    const int arow = tid >> 2, aseg = tid & 3;       // A: 128 rows x 4 8-col segs
    const int brow = tid >> 5, bseg = tid & 31;      // B: rows brow, brow+16

    const __nv_bfloat16* gAh = Ah + (size_t)(m0 + arow) * K + aseg * 8;
    const __nv_bfloat16* gAl = Al + (size_t)(m0 + arow) * K + aseg * 8;
    const __nv_bfloat16* gBh = Bh + (size_t)brow * N + n0 + bseg * 8;
    const __nv_bfloat16* gBl = Bl + (size_t)brow * N + n0 + bseg * 8;
    const uint32_t dA = arow * (A_STRIDE * 2) + aseg * 16;
    const uint32_t dB = brow * (B_STRIDE * 2) + bseg * 16;

    float acc[2][8][4];
    #pragma unroll
    for (int mt = 0; mt < 2; ++mt)
        #pragma unroll
        for (int nt = 0; nt < 8; ++nt)
            #pragma unroll
            for (int q = 0; q < 4; ++q) acc[mt][nt][q] = 0.f;

    auto issue = [&](int cc, int st) {
        const uint32_t stb = sb + (uint32_t)st * STAGE_BYTES;
        const size_t ka = (size_t)cc * 32;
        cp16(stb + dA,          gAh + ka);
        cp16(stb + OFF_AL + dA, gAl + ka);
        const size_t kb = (size_t)cc * 32 * N;
        #pragma unroll
        for (int i = 0; i < 2; ++i) {
            cp16(stb + OFF_BH + dB + i * 16 * (B_STRIDE * 2), gBh + kb + (size_t)i * 16 * N);
            cp16(stb + OFF_BL + dB + i * 16 * (B_STRIDE * 2), gBl + kb + (size_t)i * 16 * N);
        }
        cp_commit();
    };

    issue(0, 0);
    if (NC > 1) issue(1, 1);
    if (NC > 2) issue(2, 2);

    const uint32_t aRow = ((wm * 32 + (lane & 15)) * A_STRIDE + (lane >> 4) * 8) * 2;
    const int km = (lane & 7) + ((lane >> 3) & 1) * 8;
    const uint32_t bCol = OFF_BH + (km * B_STRIDE + wn * 64 + (lane >> 4) * 8) * 2;

    for (int c = 0; c < NC; ++c) {
        if (c + 2 < NC) cp_wait<2>();
        else if (c + 1 < NC) cp_wait<1>();
        else cp_wait<0>();
        __syncthreads();
        // stage (c+3)&3 == (c-1)&3, whose readers all passed the sync above
        if (c + 3 < NC) issue(c + 3, (c + 3) & 3);

        const uint32_t stb = sb + (uint32_t)(c & 3) * STAGE_BYTES;
        #pragma unroll
        for (int ks = 0; ks < 2; ++ks) {
            const int k0 = ks * 16;
            uint32_t ahr[2][4], alr[2][4];
            #pragma unroll
            for (int mt = 0; mt < 2; ++mt) {
                ldsm_x4(ahr[mt], stb + aRow + (mt * 16 * A_STRIDE + k0) * 2);
                ldsm_x4(alr[mt], stb + OFF_AL + aRow + (mt * 16 * A_STRIDE + k0) * 2);
            }
            #pragma unroll
            for (int j = 0; j < 4; ++j) {
                uint32_t bh4[4], bl4[4];
                const uint32_t ad = stb + bCol + (k0 * B_STRIDE + j * 16) * 2;
                ldsm_x4_t(bh4, ad);
                ldsm_x4_t(bl4, ad + B_BYTES);
                #pragma unroll
                for (int mt = 0; mt < 2; ++mt)
                    #pragma unroll
                    for (int u = 0; u < 2; ++u) {
                        mma_bf16(acc[mt][j * 2 + u], ahr[mt], bh4 + u * 2);
                        mma_bf16(acc[mt][j * 2 + u], ahr[mt], bl4 + u * 2);
                        mma_bf16(acc[mt][j * 2 + u], alr[mt], bh4 + u * 2);
                    }
            }
        }
    }

    const int row = m0 + wm * 32 + (lane >> 2);
    const int colb = n0 + wn * 64 + (lane & 3) * 2;
    #pragma unroll
    for (int nt = 0; nt < 8; ++nt) {
        float2 bv = make_float2(0.f, 0.f);
        if (bias) bv = *(const float2*)(bias + colb + nt * 8);
        #pragma unroll
        for (int mt = 0; mt < 2; ++mt) {
            const float* d = acc[mt][nt];
            const float v00 = d[0] + bv.x, v01 = d[1] + bv.y;
            const float v10 = d[2] + bv.x, v11 = d[3] + bv.y;
            const size_t i0 = (size_t)(row + mt * 16) * N + colb + nt * 8;
            const size_t i1 = (size_t)(row + mt * 16 + 8) * N + colb + nt * 8;
            if (Ch) {
                uint32_t h0 = pack_hi2(v00, v01), l0 = pack_lo2(v00, v01, h0);
                uint32_t h1 = pack_hi2(v10, v11), l1 = pack_lo2(v10, v11, h1);
                *(uint32_t*)&Ch[i0] = h0; *(uint32_t*)&Cl[i0] = l0;
                *(uint32_t*)&Ch[i1] = h1; *(uint32_t*)&Cl[i1] = l1;
            } else {
                *(float2*)&C[i0] = make_float2(v00, v01);
                *(float2*)&C[i1] = make_float2(v10, v11);
            }
        }
    }
}

// ---------------------------------------------------------------------------
// Tensor-core sparse attention (unchanged R9 win).
// ---------------------------------------------------------------------------
#define KSTR 72
#define SQH 0
#define SQL (64 * KSTR * 2)
#define SKH (2 * 64 * KSTR * 2)
#define SKL (SKH + 224 * KSTR * 2)
#define SVH (SKL + 224 * KSTR * 2)
#define SVL (SVH + 224 * KSTR * 2)
#define SRED (SVL + 224 * KSTR * 2)
#define SO  SKH
#define ATTN_SMEM (SRED + 1024)

__global__ __launch_bounds__(256, 1)
void attn_mma(const __nv_bfloat16* __restrict__ qh_, const __nv_bfloat16* __restrict__ ql_,
              __nv_bfloat16* __restrict__ oh, __nv_bfloat16* __restrict__ ol)
{
    const int t0 = blockIdx.x * 64;
    const int h  = blockIdx.y;
    const int b  = blockIdx.z;
    const int tid = threadIdx.x;
    const int lane = tid & 31, wid = tid >> 5;
    const int mtile = wid & 3, half = wid >> 2;

    extern __shared__ char sm[];
    const uint32_t sb = smem_u32(sm);
    const size_t baseBT = (size_t)b * TT;
    const int hoff = h * HD;

    for (int idx = tid; idx < 64 * 8; idx += 256) {
        const int r = idx >> 3, c = (idx & 7) * 8;
        const size_t go = (baseBT + t0 + r) * D3 + hoff + c;
        const uint32_t off = (r * KSTR + c) * 2;
        cp16(sb + SQH + off, qh_ + go);
        cp16(sb + SQL + off, ql_ + go);
    }
    for (int idx = tid; idx < 224 * 8; idx += 256) {
        const int r = idx >> 3, c = (idx & 7) * 8;
        int t = 0; bool valid = false;
        if (r < 128)      { t = r * 16;              valid = true; }
        else if (r < 207) { t = t0 - 15 + (r - 128); valid = (t >= 0); }
        if (t < 0) t = 0;
        const size_t go = (baseBT + t) * D3 + hoff + c;
        const uint32_t off = (r * KSTR + c) * 2;
        cp16z(sb + SKH + off, qh_ + go + 1024, valid);
        cp16z(sb + SKL + off, ql_ + go + 1024, valid);
        cp16z(sb + SVH + off, qh_ + go + 2048, valid);
        cp16z(sb + SVL + off, ql_ + go + 2048, valid);
    }
    cp_commit();
    cp_wait<0>();
    __syncthreads();

    uint32_t qh[4][4], ql[4][4];
    const uint32_t aQ = sb + SQH + ((mtile * 16 + (lane & 15)) * KSTR + (lane >> 4) * 8) * 2;
    #pragma unroll
    for (int kc = 0; kc < 4; ++kc) {
        ldsm_x4(qh[kc], aQ + kc * 32);
        ldsm_x4(ql[kc], aQ + (SQL - SQH) + kc * 32);
    }

    const uint32_t bK = sb + SKH +
        ((half * 112 + (lane & 7) + ((lane >> 4) & 1) * 8) * KSTR + ((lane >> 3) & 1) * 8) * 2;

    float cf[14][4];
    #pragma unroll
    for (int j = 0; j < 14; ++j)
        #pragma unroll
        for (int e = 0; e < 4; ++e) cf[j][e] = 0.f;

    #pragma unroll
    for (int jj = 0; jj < 7; ++jj) {
        #pragma unroll
        for (int kc = 0; kc < 4; ++kc) {
            uint32_t kh4[4], kl4[4];
            const uint32_t ad = bK + (jj * 16 * KSTR + kc * 16) * 2;
            ldsm_x4(kh4, ad);
            ldsm_x4(kl4, ad + (SKL - SKH));
            mma_bf16(cf[2 * jj],     qh[kc], kh4 + 0);
            mma_bf16(cf[2 * jj],     qh[kc], kl4 + 0);
            mma_bf16(cf[2 * jj],     ql[kc], kh4 + 0);
            mma_bf16(cf[2 * jj + 1], qh[kc], kh4 + 2);
            mma_bf16(cf[2 * jj + 1], qh[kc], kl4 + 2);
            mma_bf16(cf[2 * jj + 1], ql[kc], kh4 + 2);
        }
    }
    #pragma unroll
    for (int j = 0; j < 14; ++j)
        #pragma unroll
        for (int e = 0; e < 4; ++e) cf[j][e] *= 0.125f;

    const int r0 = mtile * 16 + (lane >> 2);
    const int r1 = r0 + 8;
    float* sMax = (float*)(sm + SRED);
    float* sSum = (float*)(sm + SRED + 512);
    const int jg = (half == 0) ? 14 : 2;

    float gm0 = -1e30f, gm1 = -1e30f;
    for (int j = 0; j < jg; ++j) {
        gm0 = fmaxf(gm0, fmaxf(cf[j][0], cf[j][1]));
        gm1 = fmaxf(gm1, fmaxf(cf[j][2], cf[j][3]));
    }
    gm0 = fmaxf(gm0, __shfl_xor_sync(0xffffffffu, gm0, 1));
    gm0 = fmaxf(gm0, __shfl_xor_sync(0xffffffffu, gm0, 2));
    gm1 = fmaxf(gm1, __shfl_xor_sync(0xffffffffu, gm1, 1));
    gm1 = fmaxf(gm1, __shfl_xor_sync(0xffffffffu, gm1, 2));
    if ((lane & 3) == 0) { sMax[half * 64 + r0] = gm0; sMax[half * 64 + r1] = gm1; }
    __syncthreads();
    const float M0 = fmaxf(sMax[r0], sMax[64 + r0]);
    const float M1 = fmaxf(sMax[r1], sMax[64 + r1]);

    float gs0 = 0.f, gs1 = 0.f;
    for (int j = 0; j < jg; ++j) {
        cf[j][0] = __expf(cf[j][0] - M0); cf[j][1] = __expf(cf[j][1] - M0);
        cf[j][2] = __expf(cf[j][2] - M1); cf[j][3] = __expf(cf[j][3] - M1);
        gs0 += cf[j][0] + cf[j][1];
        gs1 += cf[j][2] + cf[j][3];
    }
    gs0 += __shfl_xor_sync(0xffffffffu, gs0, 1);
    gs0 += __shfl_xor_sync(0xffffffffu, gs0, 2);
    gs1 += __shfl_xor_sync(0xffffffffu, gs1, 1);
    gs1 += __shfl_xor_sync(0xffffffffu, gs1, 2);
    if ((lane & 3) == 0) { sSum[half * 64 + r0] = gs0; sSum[half * 64 + r1] = gs1; }

    if (half == 1) {
        float lm0 = -1e30f, lm1 = -1e30f;
        #pragma unroll
        for (int j = 2; j < 14; ++j) {
            const int c0 = (14 + j) * 8 + (lane & 3) * 2 - 128;
            const int c1 = c0 + 1;
            if ((unsigned)(c0 - r0) > 15u) cf[j][0] = -1e30f;
            if ((unsigned)(c1 - r0) > 15u) cf[j][1] = -1e30f;
            if ((unsigned)(c0 - r1) > 15u) cf[j][2] = -1e30f;
            if ((unsigned)(c1 - r1) > 15u) cf[j][3] = -1e30f;
            lm0 = fmaxf(lm0, fmaxf(cf[j][0], cf[j][1]));
            lm1 = fmaxf(lm1, fmaxf(cf[j][2], cf[j][3]));
        }
        lm0 = fmaxf(lm0, __shfl_xor_sync(0xffffffffu, lm0, 1));
        lm0 = fmaxf(lm0, __shfl_xor_sync(0xffffffffu, lm0, 2));
        lm1 = fmaxf(lm1, __shfl_xor_sync(0xffffffffu, lm1, 1));
        lm1 = fmaxf(lm1, __shfl_xor_sync(0xffffffffu, lm1, 2));
        float ls0 = 0.f, ls1 = 0.f;
        #pragma unroll
        for (int j = 2; j < 14; ++j) {
            cf[j][0] = __expf(cf[j][0] - lm0); cf[j][1] = __expf(cf[j][1] - lm0);
            cf[j][2] = __expf(cf[j][2] - lm1); cf[j][3] = __expf(cf[j][3] - lm1);
            ls0 += cf[j][0] + cf[j][1];
            ls1 += cf[j][2] + cf[j][3];
        }
        ls0 += __shfl_xor_sync(0xffffffffu, ls0, 1);
        ls0 += __shfl_xor_sync(0xffffffffu, ls0, 2);
        ls1 += __shfl_xor_sync(0xffffffffu, ls1, 1);
        ls1 += __shfl_xor_sync(0xffffffffu, ls1, 2);
        const float il0 = 1.f / ls0, il1 = 1.f / ls1;
        #pragma unroll
        for (int j = 2; j < 14; ++j) {
            cf[j][0] *= il0; cf[j][1] *= il0;
            cf[j][2] *= il1; cf[j][3] *= il1;
        }
    }
    __syncthreads();
    const float iv0 = 1.f / (sSum[r0] + sSum[64 + r0]);
    const float iv1 = 1.f / (sSum[r1] + sSum[64 + r1]);
    for (int j = 0; j < jg; ++j) {
        cf[j][0] *= iv0; cf[j][1] *= iv0;
        cf[j][2] *= iv1; cf[j][3] *= iv1;
    }

    float of[8][4];
    #pragma unroll
    for (int nt = 0; nt < 8; ++nt)
        #pragma unroll
        for (int e = 0; e < 4; ++e) of[nt][e] = 0.f;

    const int km = (lane & 7) + ((lane >> 3) & 1) * 8;
    const uint32_t bV = sb + SVH + ((half * 112 + km) * KSTR + (lane >> 4) * 8) * 2;

    #pragma unroll
    for (int kc2 = 0; kc2 < 7; ++kc2) {
        const int j0 = 2 * kc2, j1 = j0 + 1;
        uint32_t ph[4], pl[4];
        ph[0] = pack_hi2(cf[j0][0], cf[j0][1]); pl[0] = pack_lo2(cf[j0][0], cf[j0][1], ph[0]);
        ph[1] = pack_hi2(cf[j0][2], cf[j0][3]); pl[1] = pack_lo2(cf[j0][2], cf[j0][3], ph[1]);
        ph[2] = pack_hi2(cf[j1][0], cf[j1][1]); pl[2] = pack_lo2(cf[j1][0], cf[j1][1], ph[2]);
        ph[3] = pack_hi2(cf[j1][2], cf[j1][3]); pl[3] = pack_lo2(cf[j1][2], cf[j1][3], ph[3]);
        #pragma unroll
        for (int nd2 = 0; nd2 < 4; ++nd2) {
            uint32_t vh4[4], vl4[4];
            const uint32_t ad = bV + (kc2 * 16 * KSTR + nd2 * 16) * 2;
            ldsm_x4_t(vh4, ad);
            ldsm_x4_t(vl4, ad + (SVL - SVH));
            mma_bf16(of[2 * nd2],     ph, vh4 + 0);
            mma_bf16(of[2 * nd2],     ph, vl4 + 0);
            mma_bf16(of[2 * nd2],     pl, vh4 + 0);
            mma_bf16(of[2 * nd2 + 1], ph, vh4 + 2);
            mma_bf16(of[2 * nd2 + 1], ph, vl4 + 2);
            mma_bf16(of[2 * nd2 + 1], pl, vh4 + 2);
        }
    }

    float* sO = (float*)(sm + SO);
    const int rl = lane >> 2, cb = (lane & 3) * 2;
    const int base0 = ((half * 4 + mtile) * 16 + rl) * 64;
    #pragma unroll
    for (int nt = 0; nt < 8; ++nt) {
        sO[base0 + nt * 8 + cb]     = of[nt][0];
        sO[base0 + nt * 8 + cb + 1] = of[nt][1];
        sO[base0 + 8 * 64 + nt * 8 + cb]     = of[nt][2];
        sO[base0 + 8 * 64 + nt * 8 + cb + 1] = of[nt][3];
    }
    __syncthreads();

    const int qi = tid >> 2, cg = (tid & 3) * 16;
    #pragma unroll
    for (int i = 0; i < 4; ++i) {
        const int c = cg + i * 4;
        const float4 a = *(float4*)&sO[qi * 64 + c];
        const float4 bq = *(float4*)&sO[(64 + qi) * 64 + c];
        float4 o = make_float4(a.x + bq.x, a.y + bq.y, a.z + bq.z, a.w + bq.w);
        uint2 hi, lo; cvt8(o, hi, lo);
        const size_t off = (baseBT + t0 + qi) * DD + hoff + c;
        *(uint2*)&oh[off] = hi;
        *(uint2*)&ol[off] = lo;
    }
}

// ---------------------------------------------------------------------------
extern "C" void kernel_launch(void* const* d_in, const int* in_sizes, int n_in,
                              void* d_out, int out_size)
{
    const float* x      = (const float*)d_in[0];
    const float* w_qkv  = (const float*)d_in[1];
    const float* w_proj = (const float*)d_in[2];
    const float* b_proj = (const float*)d_in[3];
    float* out = (float*)d_out;

    __nv_bfloat16 *qkvh, *qkvl, *xh, *xl, *wqh, *wql, *wph, *wpl, *ath, *atl;
    cudaGetSymbolAddress((void**)&qkvh, g_qkvh);
    cudaGetSymbolAddress((void**)&qkvl, g_qkvl);
    cudaGetSymbolAddress((void**)&xh,  g_xh);
    cudaGetSymbolAddress((void**)&xl,  g_xl);
    cudaGetSymbolAddress((void**)&wqh, g_wqh);
    cudaGetSymbolAddress((void**)&wql, g_wql);
    cudaGetSymbolAddress((void**)&wph, g_wph);
    cudaGetSymbolAddress((void**)&wpl, g_wpl);
    cudaGetSymbolAddress((void**)&ath, g_ath);
    cudaGetSymbolAddress((void**)&atl, g_atl);

    const int M = BB * TT;  // 4096

    cudaFuncSetAttribute(gemm_bf16x3, cudaFuncAttributeMaxDynamicSharedMemorySize, GEMM_SMEM);
    cudaFuncSetAttribute(attn_mma, cudaFuncAttributeMaxDynamicSharedMemorySize, ATTN_SMEM);

    // 0) split all inputs/weights into bf16 hi/lo (one launch)
    cvt3<<<1184, 256>>>(x, w_qkv, w_proj, xh, xl, wqh, wql, wph, wpl);

    // 1) qkv = x @ w_qkv  (bf16 hi/lo out)
    gemm_bf16x3<<<dim3(D3 / 256, M / 128), 512, GEMM_SMEM>>>(
        xh, xl, wqh, wql, nullptr, qkvh, qkvl, M, D3, DD, nullptr);

    // 2) tensor-core sparse attention
    attn_mma<<<dim3(TT / 64, HH, BB), 256, ATTN_SMEM>>>(qkvh, qkvl, ath, atl);

    // 3) out = attn @ w_proj + b_proj (fp32 out)
    gemm_bf16x3<<<dim3(DD / 256, M / 128), 512, GEMM_SMEM>>>(
        ath, atl, wph, wpl, out, nullptr, nullptr, M, DD, DD, b_proj);
}